// round 1
// baseline (speedup 1.0000x reference)
#include <cuda_runtime.h>
#include <math.h>

// ---------------------------------------------------------------------------
// Attention block: GroupNorm -> q,k,v (1x1 conv) -> softmax(q^T k / sqrt(C)) V
//                  -> proj (1x1 conv) + residual
// B=16, C=512, H=W=32 (HW=1024), 32 groups, eps=1e-6
// ---------------------------------------------------------------------------

#define B_ 16
#define C_ 512
#define HW_ 1024
#define NG_ 32

// Scratch (device globals; allocation is forbidden)
__device__ float g_xn[(long long)B_ * C_ * HW_];
__device__ float g_q [(long long)B_ * C_ * HW_];
__device__ float g_k [(long long)B_ * C_ * HW_];
__device__ float g_v [(long long)B_ * C_ * HW_];
__device__ float g_e [(long long)B_ * HW_ * HW_];
__device__ float g_o [(long long)B_ * C_ * HW_];

// ---------------------------------------------------------------------------
// Reductions
// ---------------------------------------------------------------------------
__inline__ __device__ float warp_sum(float v) {
    #pragma unroll
    for (int o = 16; o > 0; o >>= 1) v += __shfl_xor_sync(0xffffffffu, v, o);
    return v;
}
__inline__ __device__ float warp_max(float v) {
    #pragma unroll
    for (int o = 16; o > 0; o >>= 1) v = fmaxf(v, __shfl_xor_sync(0xffffffffu, v, o));
    return v;
}

// ---------------------------------------------------------------------------
// GroupNorm: one block per (b, g). Channels of a group are contiguous, so the
// group's 16*1024 = 16384 floats are a contiguous slab at bg*16384.
// ---------------------------------------------------------------------------
__global__ void groupnorm_kernel(const float* __restrict__ x,
                                 const float* __restrict__ gamma,
                                 const float* __restrict__ beta,
                                 float* __restrict__ xn)
{
    const int GSZ = (C_ / NG_) * HW_;   // 16384
    int bg = blockIdx.x;
    int g = bg & (NG_ - 1);
    long long base = (long long)bg * GSZ;
    int tid = threadIdx.x;

    float s = 0.f, sq = 0.f;
    for (int e = tid * 4; e < GSZ; e += 256 * 4) {
        float4 v4 = *reinterpret_cast<const float4*>(&x[base + e]);
        s  += v4.x + v4.y + v4.z + v4.w;
        sq += v4.x * v4.x + v4.y * v4.y + v4.z * v4.z + v4.w * v4.w;
    }
    __shared__ float shs[8], shq[8];
    s  = warp_sum(s);
    sq = warp_sum(sq);
    int wid = tid >> 5, lid = tid & 31;
    if (lid == 0) { shs[wid] = s; shq[wid] = sq; }
    __syncthreads();
    if (wid == 0) {
        float a = (lid < 8) ? shs[lid] : 0.f;
        float b = (lid < 8) ? shq[lid] : 0.f;
        a = warp_sum(a); b = warp_sum(b);
        if (lid == 0) { shs[0] = a; shq[0] = b; }
    }
    __syncthreads();
    float mean = shs[0] / (float)GSZ;
    float var  = shq[0] / (float)GSZ - mean * mean;
    float inv  = rsqrtf(var + 1e-6f);

    for (int e = tid * 4; e < GSZ; e += 256 * 4) {
        int c = g * (C_ / NG_) + (e >> 10);   // 1024 spatial per channel
        float ga = gamma[c] * inv;
        float be = beta[c];
        float4 v4 = *reinterpret_cast<const float4*>(&x[base + e]);
        float4 o4;
        o4.x = (v4.x - mean) * ga + be;
        o4.y = (v4.y - mean) * ga + be;
        o4.z = (v4.z - mean) * ga + be;
        o4.w = (v4.w - mean) * ga + be;
        *reinterpret_cast<float4*>(&xn[base + e]) = o4;
    }
}

// ---------------------------------------------------------------------------
// Generic batched SGEMM: C[m,n] = alpha * sum_k Ae(m,k)*Be(k,n) + bias[m] + R
//   TA=false: A is M x K (k contiguous).  TA=true: A is K x M (m contiguous).
//   TB=false: B is K x N (n contiguous).  TB=true: B is N x K (k contiguous).
// Tile 64x64x16, 256 threads, 4x4 per thread.
// ---------------------------------------------------------------------------
#define BM 64
#define BN 64
#define BK 16

template<bool TA, bool TB, bool HAS_BIAS, bool HAS_RES>
__global__ void sgemm_kernel(const float* __restrict__ A,
                             const float* __restrict__ Bm,
                             float* __restrict__ Cm,
                             const float* __restrict__ bias,
                             const float* __restrict__ resid,
                             int M, int N, int K, float alpha,
                             long long strideA, long long strideB, long long strideC)
{
    __shared__ float As[BK][BM + 4];
    __shared__ float Bs[BK][BN + 4];

    int bz = blockIdx.z;
    const float* Ap = A  + (long long)bz * strideA;
    const float* Bp = Bm + (long long)bz * strideB;
    float*       Cp = Cm + (long long)bz * strideC;
    const float* Rp = HAS_RES ? (resid + (long long)bz * strideC) : nullptr;

    int n0 = blockIdx.x * BN;
    int m0 = blockIdx.y * BM;
    int tid = threadIdx.x;
    int tr = tid >> 4;          // 0..15 -> m micro-row
    int tc = tid & 15;          // 0..15 -> n micro-col

    float acc[4][4] = {};

    for (int k0 = 0; k0 < K; k0 += BK) {
        // ---- load A tile into As[k][m] ----
        if (!TA) {
            int m  = tid >> 2;           // 0..63
            int k4 = (tid & 3) * 4;      // 0,4,8,12
            float4 av = *reinterpret_cast<const float4*>(
                &Ap[(long long)(m0 + m) * K + k0 + k4]);
            As[k4 + 0][m] = av.x; As[k4 + 1][m] = av.y;
            As[k4 + 2][m] = av.z; As[k4 + 3][m] = av.w;
        } else {
            int k  = tid >> 4;           // 0..15
            int m4 = (tid & 15) * 4;
            float4 av = *reinterpret_cast<const float4*>(
                &Ap[(long long)(k0 + k) * M + m0 + m4]);
            *reinterpret_cast<float4*>(&As[k][m4]) = av;
        }
        // ---- load B tile into Bs[k][n] ----
        if (!TB) {
            int k  = tid >> 4;
            int n4 = (tid & 15) * 4;
            float4 bv = *reinterpret_cast<const float4*>(
                &Bp[(long long)(k0 + k) * N + n0 + n4]);
            *reinterpret_cast<float4*>(&Bs[k][n4]) = bv;
        } else {
            int n  = tid >> 2;           // 0..63
            int k4 = (tid & 3) * 4;
            float4 bv = *reinterpret_cast<const float4*>(
                &Bp[(long long)(n0 + n) * K + k0 + k4]);
            Bs[k4 + 0][n] = bv.x; Bs[k4 + 1][n] = bv.y;
            Bs[k4 + 2][n] = bv.z; Bs[k4 + 3][n] = bv.w;
        }
        __syncthreads();

        #pragma unroll
        for (int kk = 0; kk < BK; kk++) {
            float a[4], b[4];
            #pragma unroll
            for (int i = 0; i < 4; i++) a[i] = As[kk][tr * 4 + i];
            #pragma unroll
            for (int j = 0; j < 4; j++) b[j] = Bs[kk][tc * 4 + j];
            #pragma unroll
            for (int i = 0; i < 4; i++)
                #pragma unroll
                for (int j = 0; j < 4; j++)
                    acc[i][j] += a[i] * b[j];
        }
        __syncthreads();
    }

    #pragma unroll
    for (int i = 0; i < 4; i++) {
        int m = m0 + tr * 4 + i;
        float bi = HAS_BIAS ? bias[m] : 0.f;
        long long off = (long long)m * N + n0 + tc * 4;
        float r0 = 0.f, r1 = 0.f, r2 = 0.f, r3 = 0.f;
        if (HAS_RES) {
            float4 rv = *reinterpret_cast<const float4*>(&Rp[off]);
            r0 = rv.x; r1 = rv.y; r2 = rv.z; r3 = rv.w;
        }
        float4 o4;
        o4.x = acc[i][0] * alpha + bi + r0;
        o4.y = acc[i][1] * alpha + bi + r1;
        o4.z = acc[i][2] * alpha + bi + r2;
        o4.w = acc[i][3] * alpha + bi + r3;
        *reinterpret_cast<float4*>(&Cp[off]) = o4;
    }
}

// ---------------------------------------------------------------------------
// Row softmax over the last dim (1024) of energy, in-place.
// One block per row (b*1024 + i), 256 threads x 4 elements.
// ---------------------------------------------------------------------------
__global__ void softmax_kernel(float* __restrict__ e)
{
    long long row = (long long)blockIdx.x * HW_;
    float* p = e + row;
    int t = threadIdx.x;

    float4 v4 = *reinterpret_cast<const float4*>(&p[t * 4]);
    float m = fmaxf(fmaxf(v4.x, v4.y), fmaxf(v4.z, v4.w));
    __shared__ float sh[8];
    m = warp_max(m);
    int wid = t >> 5, lid = t & 31;
    if (lid == 0) sh[wid] = m;
    __syncthreads();
    if (wid == 0) {
        float a = (lid < 8) ? sh[lid] : -3.4e38f;
        a = warp_max(a);
        if (lid == 0) sh[0] = a;
    }
    __syncthreads();
    m = sh[0];
    __syncthreads();

    v4.x = __expf(v4.x - m);
    v4.y = __expf(v4.y - m);
    v4.z = __expf(v4.z - m);
    v4.w = __expf(v4.w - m);
    float s = v4.x + v4.y + v4.z + v4.w;
    s = warp_sum(s);
    if (lid == 0) sh[wid] = s;
    __syncthreads();
    if (wid == 0) {
        float a = (lid < 8) ? sh[lid] : 0.f;
        a = warp_sum(a);
        if (lid == 0) sh[0] = a;
    }
    __syncthreads();
    float inv = 1.0f / sh[0];

    v4.x *= inv; v4.y *= inv; v4.z *= inv; v4.w *= inv;
    *reinterpret_cast<float4*>(&p[t * 4]) = v4;
}

// ---------------------------------------------------------------------------
// Launch
// ---------------------------------------------------------------------------
extern "C" void kernel_launch(void* const* d_in, const int* in_sizes, int n_in,
                              void* d_out, int out_size)
{
    const float* x     = (const float*)d_in[0];
    const float* gamma = (const float*)d_in[1];
    const float* beta  = (const float*)d_in[2];
    const float* wq    = (const float*)d_in[3];
    const float* bq    = (const float*)d_in[4];
    const float* wk    = (const float*)d_in[5];
    const float* bk    = (const float*)d_in[6];
    const float* wv    = (const float*)d_in[7];
    const float* bv    = (const float*)d_in[8];
    const float* wp    = (const float*)d_in[9];
    const float* bp    = (const float*)d_in[10];
    float* out = (float*)d_out;

    float *xn, *q, *k, *v, *e, *o;
    cudaGetSymbolAddress((void**)&xn, g_xn);
    cudaGetSymbolAddress((void**)&q,  g_q);
    cudaGetSymbolAddress((void**)&k,  g_k);
    cudaGetSymbolAddress((void**)&v,  g_v);
    cudaGetSymbolAddress((void**)&e,  g_e);
    cudaGetSymbolAddress((void**)&o,  g_o);

    const long long sCHW = (long long)C_ * HW_;        // 524288
    const long long sHWHW = (long long)HW_ * HW_;      // 1048576
    const float scale = 1.0f / sqrtf((float)C_);

    // 1) GroupNorm
    groupnorm_kernel<<<B_ * NG_, 256>>>(x, gamma, beta, xn);

    // 2) q, k, v = W (512x512) @ xn[b] (512x1024) + bias
    dim3 gq(HW_ / BN, C_ / BM, B_);
    sgemm_kernel<false, false, true, false><<<gq, 256>>>(
        wq, xn, q, bq, nullptr, C_, HW_, C_, 1.0f, 0, sCHW, sCHW);
    sgemm_kernel<false, false, true, false><<<gq, 256>>>(
        wk, xn, k, bk, nullptr, C_, HW_, C_, 1.0f, 0, sCHW, sCHW);
    sgemm_kernel<false, false, true, false><<<gq, 256>>>(
        wv, xn, v, bv, nullptr, C_, HW_, C_, 1.0f, 0, sCHW, sCHW);

    // 3) energy[b,i,j] = scale * sum_c q[b,c,i]*k[b,c,j]   (TA: q is K x M)
    dim3 ge(HW_ / BN, HW_ / BM, B_);
    sgemm_kernel<true, false, false, false><<<ge, 256>>>(
        q, k, e, nullptr, nullptr, HW_, HW_, C_, scale, sCHW, sCHW, sHWHW);

    // 4) softmax rows
    softmax_kernel<<<B_ * HW_, 256>>>(e);

    // 5) o[b,c,i] = sum_j v[b,c,j] * attn[b,i,j]   (TB: attn is N x K)
    dim3 go(HW_ / BN, C_ / BM, B_);
    sgemm_kernel<false, true, false, false><<<go, 256>>>(
        v, e, o, nullptr, nullptr, C_, HW_, HW_, 1.0f, sCHW, sHWHW, sCHW);

    // 6) out = wp @ o + bp + residual(x)
    sgemm_kernel<false, false, true, true><<<gq, 256>>>(
        wp, o, out, bp, x, C_, HW_, C_, 1.0f, 0, sCHW, sCHW);
}

// round 3
// speedup vs baseline: 2.2593x; 2.2593x over previous
#include <cuda_runtime.h>
#include <cstdint>
#include <math.h>

// ---------------------------------------------------------------------------
// Attention block: GroupNorm -> q,k,v -> softmax(q^T k / sqrt(C)) V -> proj+res
// B=16, C=512, HW=1024, 32 groups, eps=1e-6
// GEMMs on tf32 mma.sync (m16n8k8) — tcgen05 PTX is not available on the
// compute_103 PTX target this harness uses.
// ---------------------------------------------------------------------------

#define B_ 16
#define C_ 512
#define HW_ 1024
#define NG_ 32

__device__ float g_xn[(long long)B_ * C_ * HW_];
__device__ float g_q [(long long)B_ * C_ * HW_];
__device__ float g_k [(long long)B_ * C_ * HW_];
__device__ float g_v [(long long)B_ * C_ * HW_];
__device__ float g_e [(long long)B_ * HW_ * HW_];
__device__ float g_o [(long long)B_ * C_ * HW_];

__device__ __forceinline__ uint32_t tf32r(float x) {
    uint32_t u;
    asm("cvt.rna.tf32.f32 %0, %1;" : "=r"(u) : "f"(x));
    return u;
}

__inline__ __device__ float warp_sum(float v) {
    #pragma unroll
    for (int o = 16; o > 0; o >>= 1) v += __shfl_xor_sync(0xffffffffu, v, o);
    return v;
}
__inline__ __device__ float warp_max(float v) {
    #pragma unroll
    for (int o = 16; o > 0; o >>= 1) v = fmaxf(v, __shfl_xor_sync(0xffffffffu, v, o));
    return v;
}

// ---------------------------------------------------------------------------
// GroupNorm
// ---------------------------------------------------------------------------
__global__ void groupnorm_kernel(const float* __restrict__ x,
                                 const float* __restrict__ gamma,
                                 const float* __restrict__ beta,
                                 float* __restrict__ xn)
{
    const int GSZ = (C_ / NG_) * HW_;   // 16384
    int bg = blockIdx.x;
    int g = bg & (NG_ - 1);
    long long base = (long long)bg * GSZ;
    int tid = threadIdx.x;

    float s = 0.f, sq = 0.f;
    for (int e = tid * 4; e < GSZ; e += 256 * 4) {
        float4 v4 = *reinterpret_cast<const float4*>(&x[base + e]);
        s  += v4.x + v4.y + v4.z + v4.w;
        sq += v4.x * v4.x + v4.y * v4.y + v4.z * v4.z + v4.w * v4.w;
    }
    __shared__ float shs[8], shq[8];
    s = warp_sum(s); sq = warp_sum(sq);
    int wid = tid >> 5, lid = tid & 31;
    if (lid == 0) { shs[wid] = s; shq[wid] = sq; }
    __syncthreads();
    if (wid == 0) {
        float a = (lid < 8) ? shs[lid] : 0.f;
        float b = (lid < 8) ? shq[lid] : 0.f;
        a = warp_sum(a); b = warp_sum(b);
        if (lid == 0) { shs[0] = a; shq[0] = b; }
    }
    __syncthreads();
    float mean = shs[0] / (float)GSZ;
    float var  = shq[0] / (float)GSZ - mean * mean;
    float inv  = rsqrtf(var + 1e-6f);

    for (int e = tid * 4; e < GSZ; e += 256 * 4) {
        int c = g * (C_ / NG_) + (e >> 10);
        float ga = gamma[c] * inv;
        float be = beta[c];
        float4 v4 = *reinterpret_cast<const float4*>(&x[base + e]);
        float4 o4;
        o4.x = (v4.x - mean) * ga + be;
        o4.y = (v4.y - mean) * ga + be;
        o4.z = (v4.z - mean) * ga + be;
        o4.w = (v4.w - mean) * ga + be;
        *reinterpret_cast<float4*>(&xn[base + e]) = o4;
    }
}

// ---------------------------------------------------------------------------
// tf32 mma.sync batched GEMM:
//   D[m,n] = alpha * sum_k Ae(m,k)*Be(n,k) (+ bias[m]) (+ resid)
//   TA=false: Ae(m,k) = A[(m0+m)*ldA + k]   (k contiguous)
//   TA=true:  Ae(m,k) = A[k*ldA + m0+m]     (m contiguous)
//   TB same with n.
// CTA tile 128x128x32. 256 threads = 8 warps (4 x M, 2 x N), warp tile 32x64.
// ---------------------------------------------------------------------------
#define BM 128
#define BN 128
#define BK 32
#define SPAD 4

__device__ __forceinline__ void mma_tf32(float c[4],
                                         const uint32_t a[4],
                                         const uint32_t b[2])
{
    asm volatile(
        "mma.sync.aligned.m16n8k8.row.col.f32.tf32.tf32.f32 "
        "{%0,%1,%2,%3}, {%4,%5,%6,%7}, {%8,%9}, {%0,%1,%2,%3};"
        : "+f"(c[0]), "+f"(c[1]), "+f"(c[2]), "+f"(c[3])
        : "r"(a[0]), "r"(a[1]), "r"(a[2]), "r"(a[3]), "r"(b[0]), "r"(b[1]));
}

template<bool TA, bool TB, bool HAS_BIAS, bool HAS_RES>
__global__ __launch_bounds__(256) void mm_gemm(
    const float* __restrict__ A, const float* __restrict__ Bm,
    float* __restrict__ Cm, const float* __restrict__ bias,
    const float* __restrict__ resid,
    int K, int ldA, int ldB, int N, float alpha,
    long long sA, long long sB, long long sC)
{
    __shared__ uint32_t As[BK][BM + SPAD];
    __shared__ uint32_t Bs[BK][BN + SPAD];

    int tid = threadIdx.x, wid = tid >> 5, lane = tid & 31;
    int g = lane >> 2, t = lane & 3;          // mma fragment coords
    int wm = (wid & 3) * 32;                  // warp m offset in tile
    int wn = (wid >> 2) * 64;                 // warp n offset in tile
    int n0 = blockIdx.x * BN;
    int m0 = blockIdx.y * BM;
    int bz = blockIdx.z;
    const float* Ap = A  + (long long)bz * sA;
    const float* Bp = Bm + (long long)bz * sB;
    float*       Cp = Cm + (long long)bz * sC;

    float acc[2][8][4] = {};

    for (int k0 = 0; k0 < K; k0 += BK) {
        // ---- A tile -> As[k][m] ----
        if (!TA) {
            #pragma unroll
            for (int it = 0; it < 4; it++) {
                int idx = tid + it * 256;
                int m = idx >> 3, kq = idx & 7;
                float4 v = *reinterpret_cast<const float4*>(
                    &Ap[(long long)(m0 + m) * ldA + k0 + kq * 4]);
                As[kq * 4 + 0][m] = tf32r(v.x);
                As[kq * 4 + 1][m] = tf32r(v.y);
                As[kq * 4 + 2][m] = tf32r(v.z);
                As[kq * 4 + 3][m] = tf32r(v.w);
            }
        } else {
            #pragma unroll
            for (int it = 0; it < 4; it++) {
                int idx = tid + it * 256;
                int k = idx >> 5, m4 = (idx & 31) * 4;
                float4 v = *reinterpret_cast<const float4*>(
                    &Ap[(long long)(k0 + k) * ldA + m0 + m4]);
                As[k][m4 + 0] = tf32r(v.x);
                As[k][m4 + 1] = tf32r(v.y);
                As[k][m4 + 2] = tf32r(v.z);
                As[k][m4 + 3] = tf32r(v.w);
            }
        }
        // ---- B tile -> Bs[k][n] ----
        if (!TB) {
            #pragma unroll
            for (int it = 0; it < 4; it++) {
                int idx = tid + it * 256;
                int n = idx >> 3, kq = idx & 7;
                float4 v = *reinterpret_cast<const float4*>(
                    &Bp[(long long)(n0 + n) * ldB + k0 + kq * 4]);
                Bs[kq * 4 + 0][n] = tf32r(v.x);
                Bs[kq * 4 + 1][n] = tf32r(v.y);
                Bs[kq * 4 + 2][n] = tf32r(v.z);
                Bs[kq * 4 + 3][n] = tf32r(v.w);
            }
        } else {
            #pragma unroll
            for (int it = 0; it < 4; it++) {
                int idx = tid + it * 256;
                int k = idx >> 5, n4 = (idx & 31) * 4;
                float4 v = *reinterpret_cast<const float4*>(
                    &Bp[(long long)(k0 + k) * ldB + n0 + n4]);
                Bs[k][n4 + 0] = tf32r(v.x);
                Bs[k][n4 + 1] = tf32r(v.y);
                Bs[k][n4 + 2] = tf32r(v.z);
                Bs[k][n4 + 3] = tf32r(v.w);
            }
        }
        __syncthreads();

        #pragma unroll
        for (int ks = 0; ks < BK; ks += 8) {
            uint32_t afr[2][4];
            #pragma unroll
            for (int mi = 0; mi < 2; mi++) {
                int mw = wm + mi * 16 + g;
                afr[mi][0] = As[ks + t][mw];
                afr[mi][1] = As[ks + t][mw + 8];
                afr[mi][2] = As[ks + t + 4][mw];
                afr[mi][3] = As[ks + t + 4][mw + 8];
            }
            #pragma unroll
            for (int ni = 0; ni < 8; ni++) {
                uint32_t bfr[2];
                int nb = wn + ni * 8 + g;
                bfr[0] = Bs[ks + t][nb];
                bfr[1] = Bs[ks + t + 4][nb];
                #pragma unroll
                for (int mi = 0; mi < 2; mi++)
                    mma_tf32(acc[mi][ni], afr[mi], bfr);
            }
        }
        __syncthreads();
    }

    // ---- epilogue ----
    const float* Rp = HAS_RES ? (resid + (long long)bz * sC) : nullptr;
    #pragma unroll
    for (int mi = 0; mi < 2; mi++) {
        int mlo = m0 + wm + mi * 16 + g;
        int mhi = mlo + 8;
        float blo = HAS_BIAS ? bias[mlo] : 0.f;
        float bhi = HAS_BIAS ? bias[mhi] : 0.f;
        #pragma unroll
        for (int ni = 0; ni < 8; ni++) {
            long long col = n0 + wn + ni * 8 + 2 * t;
            long long olo = (long long)mlo * N + col;
            long long ohi = (long long)mhi * N + col;
            float2 vlo, vhi;
            vlo.x = acc[mi][ni][0] * alpha + blo;
            vlo.y = acc[mi][ni][1] * alpha + blo;
            vhi.x = acc[mi][ni][2] * alpha + bhi;
            vhi.y = acc[mi][ni][3] * alpha + bhi;
            if (HAS_RES) {
                float2 r0 = *reinterpret_cast<const float2*>(&Rp[olo]);
                float2 r1 = *reinterpret_cast<const float2*>(&Rp[ohi]);
                vlo.x += r0.x; vlo.y += r0.y;
                vhi.x += r1.x; vhi.y += r1.y;
            }
            *reinterpret_cast<float2*>(&Cp[olo]) = vlo;
            *reinterpret_cast<float2*>(&Cp[ohi]) = vhi;
        }
    }
}

// ---------------------------------------------------------------------------
// Row softmax over last dim (1024), in-place
// ---------------------------------------------------------------------------
__global__ void softmax_kernel(float* __restrict__ e)
{
    long long row = (long long)blockIdx.x * HW_;
    float* p = e + row;
    int t = threadIdx.x;

    float4 v4 = *reinterpret_cast<const float4*>(&p[t * 4]);
    float m = fmaxf(fmaxf(v4.x, v4.y), fmaxf(v4.z, v4.w));
    __shared__ float sh[8];
    m = warp_max(m);
    int wid = t >> 5, lid = t & 31;
    if (lid == 0) sh[wid] = m;
    __syncthreads();
    if (wid == 0) {
        float a = (lid < 8) ? sh[lid] : -3.4e38f;
        a = warp_max(a);
        if (lid == 0) sh[0] = a;
    }
    __syncthreads();
    m = sh[0];
    __syncthreads();

    v4.x = __expf(v4.x - m);
    v4.y = __expf(v4.y - m);
    v4.z = __expf(v4.z - m);
    v4.w = __expf(v4.w - m);
    float s = v4.x + v4.y + v4.z + v4.w;
    s = warp_sum(s);
    if (lid == 0) sh[wid] = s;
    __syncthreads();
    if (wid == 0) {
        float a = (lid < 8) ? sh[lid] : 0.f;
        a = warp_sum(a);
        if (lid == 0) sh[0] = a;
    }
    __syncthreads();
    float inv = 1.0f / sh[0];

    v4.x *= inv; v4.y *= inv; v4.z *= inv; v4.w *= inv;
    *reinterpret_cast<float4*>(&p[t * 4]) = v4;
}

// ---------------------------------------------------------------------------
// Launch
// ---------------------------------------------------------------------------
extern "C" void kernel_launch(void* const* d_in, const int* in_sizes, int n_in,
                              void* d_out, int out_size)
{
    const float* x     = (const float*)d_in[0];
    const float* gamma = (const float*)d_in[1];
    const float* beta  = (const float*)d_in[2];
    const float* wq    = (const float*)d_in[3];
    const float* bq    = (const float*)d_in[4];
    const float* wk    = (const float*)d_in[5];
    const float* bk    = (const float*)d_in[6];
    const float* wv    = (const float*)d_in[7];
    const float* bv    = (const float*)d_in[8];
    const float* wp    = (const float*)d_in[9];
    const float* bp    = (const float*)d_in[10];
    float* out = (float*)d_out;

    float *xn, *q, *k, *v, *e, *o;
    cudaGetSymbolAddress((void**)&xn, g_xn);
    cudaGetSymbolAddress((void**)&q,  g_q);
    cudaGetSymbolAddress((void**)&k,  g_k);
    cudaGetSymbolAddress((void**)&v,  g_v);
    cudaGetSymbolAddress((void**)&e,  g_e);
    cudaGetSymbolAddress((void**)&o,  g_o);

    const long long sCHW  = (long long)C_ * HW_;
    const long long sHWHW = (long long)HW_ * HW_;
    const float scale = 1.0f / sqrtf((float)C_);

    // 1) GroupNorm
    groupnorm_kernel<<<B_ * NG_, 256>>>(x, gamma, beta, xn);

    // 2) q,k,v[o,s] = sum_c W[o,c] * xn[c,s] + bias   (A=W, B=xn^T)
    dim3 gq(HW_ / BN, C_ / BM, B_);
    mm_gemm<false, true, true, false><<<gq, 256>>>(
        wq, xn, q, bq, nullptr, C_, C_, HW_, HW_, 1.0f, 0, sCHW, sCHW);
    mm_gemm<false, true, true, false><<<gq, 256>>>(
        wk, xn, k, bk, nullptr, C_, C_, HW_, HW_, 1.0f, 0, sCHW, sCHW);
    mm_gemm<false, true, true, false><<<gq, 256>>>(
        wv, xn, v, bv, nullptr, C_, C_, HW_, HW_, 1.0f, 0, sCHW, sCHW);

    // 3) energy[i,j] = scale * sum_c q[c,i] * k[c,j]   (A=q^T, B=k^T)
    dim3 ge(HW_ / BN, HW_ / BM, B_);
    mm_gemm<true, true, false, false><<<ge, 256>>>(
        q, k, e, nullptr, nullptr, C_, HW_, HW_, HW_, scale, sCHW, sCHW, sHWHW);

    // 4) softmax rows
    softmax_kernel<<<B_ * HW_, 256>>>(e);

    // 5) o[c,i] = sum_j v[c,j] * attn[i,j]   (A=v, B=attn)
    dim3 go(HW_ / BN, C_ / BM, B_);
    mm_gemm<false, false, false, false><<<go, 256>>>(
        v, e, o, nullptr, nullptr, HW_, HW_, HW_, HW_, 1.0f, sCHW, sHWHW, sCHW);

    // 6) out = wp @ o + bp + residual(x)   (A=wp, B=o^T)
    mm_gemm<false, true, true, true><<<gq, 256>>>(
        wp, o, out, bp, x, C_, C_, HW_, HW_, 1.0f, 0, sCHW, sCHW);
}

// round 4
// speedup vs baseline: 5.1048x; 2.2595x over previous
#include <cuda_runtime.h>
#include <cuda_bf16.h>
#include <cstdint>
#include <math.h>

// ---------------------------------------------------------------------------
// Attention block, bf16 tensor-core pipeline (mma.sync m16n8k16).
// B=16, C=512, HW=1024, 32 groups, eps=1e-6
// Dataflow arranged so every GEMM is D = A * B^T with BOTH operands
// k-contiguous bf16 -> smem fills are pure 16B cp.async copies.
//   gn_t:   x (B,C,HW) fp32 -> xn_t (B,HW,C) bf16        [transpose in smem]
//   qt/kt:  q_t[s,o] = sum_c xn_t[s,c] wq[o,c] + bq[o]
//   v:      v[o,s]   = sum_c wv[o,c] xn_t[s,c] + bv[o]
//   e:      e[i,j]   = scale * sum_c q_t[i,c] k_t[j,c]   (fp32 out)
//   softmax rows -> attn bf16
//   ot:     o_t[i,c] = sum_j attn[i,j] v[c,j]
//   proj:   out[o,s] = sum_c wp[o,c] o_t[s,c] + bp[o] + x[o,s]
// ---------------------------------------------------------------------------

#define B_ 16
#define C_ 512
#define HW_ 1024
#define NG_ 32

__device__ __nv_bfloat16 g_xnt[(long long)B_ * HW_ * C_];
__device__ __nv_bfloat16 g_qt [(long long)B_ * HW_ * C_];
__device__ __nv_bfloat16 g_kt [(long long)B_ * HW_ * C_];
__device__ __nv_bfloat16 g_v  [(long long)B_ * C_ * HW_];
__device__ float         g_e  [(long long)B_ * HW_ * HW_];
__device__ __nv_bfloat16 g_at [(long long)B_ * HW_ * HW_];
__device__ __nv_bfloat16 g_ot [(long long)B_ * HW_ * C_];
__device__ __nv_bfloat16 g_wq[C_ * C_], g_wk[C_ * C_], g_wv[C_ * C_], g_wp[C_ * C_];

__inline__ __device__ float warp_sum(float v) {
    #pragma unroll
    for (int o = 16; o > 0; o >>= 1) v += __shfl_xor_sync(0xffffffffu, v, o);
    return v;
}
__inline__ __device__ float warp_max(float v) {
    #pragma unroll
    for (int o = 16; o > 0; o >>= 1) v = fmaxf(v, __shfl_xor_sync(0xffffffffu, v, o));
    return v;
}

__device__ __forceinline__ uint32_t smem_u32(const void* p) {
    uint32_t a;
    asm("{ .reg .u64 t; cvta.to.shared.u64 t, %1; cvt.u32.u64 %0, t; }"
        : "=r"(a) : "l"(p));
    return a;
}

#define CPA16(dst, src) \
    asm volatile("cp.async.cg.shared.global [%0], [%1], 16;" :: "r"(dst), "l"(src))
#define CPA_COMMIT() asm volatile("cp.async.commit_group;" ::: "memory")

#define LDSM4(R0, R1, R2, R3, addr) \
    asm volatile("ldmatrix.sync.aligned.m8n8.x4.shared.b16 {%0,%1,%2,%3}, [%4];" \
                 : "=r"(R0), "=r"(R1), "=r"(R2), "=r"(R3) : "r"(addr))

__device__ __forceinline__ void mma_bf16(float c[4], const uint32_t a[4],
                                         uint32_t b0, uint32_t b1) {
    asm volatile(
        "mma.sync.aligned.m16n8k16.row.col.f32.bf16.bf16.f32 "
        "{%0,%1,%2,%3}, {%4,%5,%6,%7}, {%8,%9}, {%0,%1,%2,%3};"
        : "+f"(c[0]), "+f"(c[1]), "+f"(c[2]), "+f"(c[3])
        : "r"(a[0]), "r"(a[1]), "r"(a[2]), "r"(a[3]), "r"(b0), "r"(b1));
}

// ---------------------------------------------------------------------------
// Weight conversion fp32 -> bf16 (tiny prepass)
// ---------------------------------------------------------------------------
__global__ void convert_w(const float* __restrict__ wq, const float* __restrict__ wk,
                          const float* __restrict__ wv, const float* __restrict__ wp)
{
    int i = (blockIdx.x * 256 + threadIdx.x) * 4;
    if (i >= C_ * C_) return;
    #pragma unroll
    for (int j = 0; j < 4; j++) {
        g_wq[i + j] = __float2bfloat16_rn(wq[i + j]);
        g_wk[i + j] = __float2bfloat16_rn(wk[i + j]);
        g_wv[i + j] = __float2bfloat16_rn(wv[i + j]);
        g_wp[i + j] = __float2bfloat16_rn(wp[i + j]);
    }
}

// ---------------------------------------------------------------------------
// GroupNorm + transpose: x (B,C,HW) fp32 -> xn_t (B,HW,C) bf16
// One block per (b,g): slab = 16 channels x 1024 spatial, contiguous.
// ---------------------------------------------------------------------------
__global__ void gn_t_kernel(const float* __restrict__ x,
                            const float* __restrict__ gamma,
                            const float* __restrict__ beta)
{
    const int GSZ = 16 * HW_;   // 16384
    int bg = blockIdx.x;
    int b = bg >> 5, g = bg & 31;
    long long base = (long long)bg * GSZ;
    int tid = threadIdx.x;

    // pass 1: stats (coalesced)
    float s = 0.f, sq = 0.f;
    for (int e = tid * 4; e < GSZ; e += 256 * 4) {
        float4 v4 = *reinterpret_cast<const float4*>(&x[base + e]);
        s  += v4.x + v4.y + v4.z + v4.w;
        sq += v4.x * v4.x + v4.y * v4.y + v4.z * v4.z + v4.w * v4.w;
    }
    __shared__ float shs[8], shq[8];
    s = warp_sum(s); sq = warp_sum(sq);
    int wid = tid >> 5, lid = tid & 31;
    if (lid == 0) { shs[wid] = s; shq[wid] = sq; }
    __syncthreads();
    if (wid == 0) {
        float a = (lid < 8) ? shs[lid] : 0.f;
        float bb = (lid < 8) ? shq[lid] : 0.f;
        a = warp_sum(a); bb = warp_sum(bb);
        if (lid == 0) { shs[0] = a; shq[0] = bb; }
    }
    __syncthreads();
    float mean = shs[0] / (float)GSZ;
    float var  = shq[0] / (float)GSZ - mean * mean;
    float inv  = rsqrtf(var + 1e-6f);

    float ga[16], be[16];
    #pragma unroll
    for (int c = 0; c < 16; c++) {
        ga[c] = gamma[g * 16 + c] * inv;
        be[c] = beta[g * 16 + c] - mean * ga[c];
    }

    // pass 2: tiled transpose through smem
    __shared__ float tile[16][256];
    for (int s0 = 0; s0 < HW_; s0 += 256) {
        __syncthreads();
        #pragma unroll
        for (int i = 0; i < 16; i++) {
            int task = tid + i * 256;
            int c = task >> 8, sl = task & 255;
            tile[c][sl] = x[base + (long long)c * HW_ + s0 + sl];
        }
        __syncthreads();
        int sp = s0 + tid;
        union { __nv_bfloat16 h[16]; uint4 u[2]; } o;
        #pragma unroll
        for (int c = 0; c < 16; c++)
            o.h[c] = __float2bfloat16_rn(tile[c][tid] * ga[c] + be[c]);
        uint4* dst = reinterpret_cast<uint4*>(
            &g_xnt[((long long)b * HW_ + sp) * C_ + g * 16]);
        dst[0] = o.u[0];
        dst[1] = o.u[1];
    }
}

// ---------------------------------------------------------------------------
// bf16 GEMM: D[m,n] = alpha * sum_k A[m,k]*B[n,k] (+bias) (+res)
// A: M x K (k contig, bf16), B: N x K (k contig, bf16).
// CTA 128x128, BK=32, 8 warps (4M x 2N), warp tile 32x64.
// Double-buffered cp.async + ldmatrix.
// BIAS_MODE: 0 none, 1 bias[m], 2 bias[n]. OUT_BF16: output dtype.
// ---------------------------------------------------------------------------
#define BK 32
#define ROWE 40                 // padded row length in bf16 elems (80B)
#define STGE (128 * ROWE)       // elems per buffer

template<int BIAS_MODE, bool HAS_RES, bool OUT_BF16>
__global__ __launch_bounds__(256) void bf_gemm(
    const __nv_bfloat16* __restrict__ A, const __nv_bfloat16* __restrict__ Bm,
    void* __restrict__ Cv, const float* __restrict__ bias,
    const float* __restrict__ resid,
    int K, int ldA, int ldB, int N, float alpha,
    long long sA, long long sB, long long sC)
{
    __shared__ __nv_bfloat16 As[2 * STGE];
    __shared__ __nv_bfloat16 Bs[2 * STGE];

    int tid = threadIdx.x, wid = tid >> 5, lane = tid & 31;
    int g = lane >> 2, t = lane & 3;
    int wm = (wid & 3) * 32;
    int wn = (wid >> 2) * 64;
    int n0 = blockIdx.x * 128;
    int m0 = blockIdx.y * 128;
    int bz = blockIdx.z;
    const __nv_bfloat16* Ap = A  + (long long)bz * sA;
    const __nv_bfloat16* Bp = Bm + (long long)bz * sB;

    uint32_t as_base = smem_u32(As);
    uint32_t bs_base = smem_u32(Bs);

    // fill task: 512 16B-chunks per operand, 2 per thread
    int frow = tid >> 1;                 // 0..127
    int fk0  = (tid & 1) * 16;           // two chunks per row half? -> use 2 tasks
    // (use explicit 2-task loop instead)

    float acc[2][8][4];
    #pragma unroll
    for (int a = 0; a < 2; a++)
        #pragma unroll
        for (int b = 0; b < 8; b++)
            #pragma unroll
            for (int c = 0; c < 4; c++) acc[a][b][c] = 0.f;

    int nt = K / BK;

    // prologue: stage 0
    {
        #pragma unroll
        for (int i = 0; i < 2; i++) {
            int task = tid + i * 256;
            int row = task >> 2, kc = task & 3;
            CPA16(as_base + (row * ROWE + kc * 8) * 2,
                  Ap + (long long)(m0 + row) * ldA + kc * 8);
            CPA16(bs_base + (row * ROWE + kc * 8) * 2,
                  Bp + (long long)(n0 + row) * ldB + kc * 8);
        }
        CPA_COMMIT();
    }

    int buf = 0;
    for (int tt = 0; tt < nt; tt++) {
        if (tt + 1 < nt) {
            int k0 = (tt + 1) * BK;
            uint32_t ao = as_base + (buf ^ 1) * STGE * 2;
            uint32_t bo = bs_base + (buf ^ 1) * STGE * 2;
            #pragma unroll
            for (int i = 0; i < 2; i++) {
                int task = tid + i * 256;
                int row = task >> 2, kc = task & 3;
                CPA16(ao + (row * ROWE + kc * 8) * 2,
                      Ap + (long long)(m0 + row) * ldA + k0 + kc * 8);
                CPA16(bo + (row * ROWE + kc * 8) * 2,
                      Bp + (long long)(n0 + row) * ldB + k0 + kc * 8);
            }
            CPA_COMMIT();
            asm volatile("cp.async.wait_group 1;" ::: "memory");
        } else {
            asm volatile("cp.async.wait_group 0;" ::: "memory");
        }
        __syncthreads();

        uint32_t ab = as_base + buf * STGE * 2;
        uint32_t bb = bs_base + buf * STGE * 2;
        #pragma unroll
        for (int ks = 0; ks < BK; ks += 16) {
            uint32_t afr[2][4];
            #pragma unroll
            for (int mi = 0; mi < 2; mi++) {
                uint32_t addr = ab +
                    (((wm + mi * 16 + (lane & 15)) * ROWE) + ks + (lane >> 4) * 8) * 2;
                LDSM4(afr[mi][0], afr[mi][1], afr[mi][2], afr[mi][3], addr);
            }
            #pragma unroll
            for (int np = 0; np < 4; np++) {
                uint32_t b0, b1, b2, b3;
                uint32_t addr = bb +
                    (((wn + np * 16 + ((lane >> 4) << 3) + (lane & 7)) * ROWE)
                     + ks + ((lane >> 3) & 1) * 8) * 2;
                LDSM4(b0, b1, b2, b3, addr);
                mma_bf16(acc[0][np * 2], afr[0], b0, b1);
                mma_bf16(acc[1][np * 2], afr[1], b0, b1);
                mma_bf16(acc[0][np * 2 + 1], afr[0], b2, b3);
                mma_bf16(acc[1][np * 2 + 1], afr[1], b2, b3);
            }
        }
        __syncthreads();
        buf ^= 1;
    }

    // epilogue
    const float* Rp = HAS_RES ? (resid + (long long)bz * sC) : nullptr;
    float* Cf = OUT_BF16 ? nullptr : ((float*)Cv + (long long)bz * sC);
    __nv_bfloat16* Ch = OUT_BF16 ? ((__nv_bfloat16*)Cv + (long long)bz * sC) : nullptr;

    #pragma unroll
    for (int mi = 0; mi < 2; mi++) {
        int mlo = m0 + wm + mi * 16 + g;
        int mhi = mlo + 8;
        float bmlo = (BIAS_MODE == 1) ? bias[mlo] : 0.f;
        float bmhi = (BIAS_MODE == 1) ? bias[mhi] : 0.f;
        #pragma unroll
        for (int ni = 0; ni < 8; ni++) {
            int col = n0 + wn + ni * 8 + 2 * t;
            float bn0 = (BIAS_MODE == 2) ? bias[col] : 0.f;
            float bn1 = (BIAS_MODE == 2) ? bias[col + 1] : 0.f;
            float v00 = acc[mi][ni][0] * alpha + bmlo + bn0;
            float v01 = acc[mi][ni][1] * alpha + bmlo + bn1;
            float v10 = acc[mi][ni][2] * alpha + bmhi + bn0;
            float v11 = acc[mi][ni][3] * alpha + bmhi + bn1;
            long long olo = (long long)mlo * N + col;
            long long ohi = (long long)mhi * N + col;
            if (HAS_RES) {
                float2 r0 = *reinterpret_cast<const float2*>(&Rp[olo]);
                float2 r1 = *reinterpret_cast<const float2*>(&Rp[ohi]);
                v00 += r0.x; v01 += r0.y; v10 += r1.x; v11 += r1.y;
            }
            if (OUT_BF16) {
                __nv_bfloat162 plo(__float2bfloat16_rn(v00), __float2bfloat16_rn(v01));
                __nv_bfloat162 phi(__float2bfloat16_rn(v10), __float2bfloat16_rn(v11));
                *reinterpret_cast<__nv_bfloat162*>(&Ch[olo]) = plo;
                *reinterpret_cast<__nv_bfloat162*>(&Ch[ohi]) = phi;
            } else {
                *reinterpret_cast<float2*>(&Cf[olo]) = make_float2(v00, v01);
                *reinterpret_cast<float2*>(&Cf[ohi]) = make_float2(v10, v11);
            }
        }
    }
}

// ---------------------------------------------------------------------------
// Row softmax: e fp32 (1024 per row) -> attn bf16
// ---------------------------------------------------------------------------
__global__ void softmax_kernel(const float* __restrict__ e,
                               __nv_bfloat16* __restrict__ at)
{
    long long row = (long long)blockIdx.x * HW_;
    const float* p = e + row;
    int t = threadIdx.x;

    float4 v4 = *reinterpret_cast<const float4*>(&p[t * 4]);
    float m = fmaxf(fmaxf(v4.x, v4.y), fmaxf(v4.z, v4.w));
    __shared__ float sh[8];
    m = warp_max(m);
    int wid = t >> 5, lid = t & 31;
    if (lid == 0) sh[wid] = m;
    __syncthreads();
    if (wid == 0) {
        float a = (lid < 8) ? sh[lid] : -3.4e38f;
        a = warp_max(a);
        if (lid == 0) sh[0] = a;
    }
    __syncthreads();
    m = sh[0];
    __syncthreads();

    v4.x = __expf(v4.x - m);
    v4.y = __expf(v4.y - m);
    v4.z = __expf(v4.z - m);
    v4.w = __expf(v4.w - m);
    float s = v4.x + v4.y + v4.z + v4.w;
    s = warp_sum(s);
    if (lid == 0) sh[wid] = s;
    __syncthreads();
    if (wid == 0) {
        float a = (lid < 8) ? sh[lid] : 0.f;
        a = warp_sum(a);
        if (lid == 0) sh[0] = a;
    }
    __syncthreads();
    float inv = 1.0f / sh[0];

    __nv_bfloat162 p0(__float2bfloat16_rn(v4.x * inv), __float2bfloat16_rn(v4.y * inv));
    __nv_bfloat162 p1(__float2bfloat16_rn(v4.z * inv), __float2bfloat16_rn(v4.w * inv));
    __nv_bfloat162* dst = reinterpret_cast<__nv_bfloat162*>(&at[row + t * 4]);
    dst[0] = p0;
    dst[1] = p1;
}

// ---------------------------------------------------------------------------
// Launch
// ---------------------------------------------------------------------------
extern "C" void kernel_launch(void* const* d_in, const int* in_sizes, int n_in,
                              void* d_out, int out_size)
{
    const float* x     = (const float*)d_in[0];
    const float* gamma = (const float*)d_in[1];
    const float* beta  = (const float*)d_in[2];
    const float* wq    = (const float*)d_in[3];
    const float* bq    = (const float*)d_in[4];
    const float* wk    = (const float*)d_in[5];
    const float* bk    = (const float*)d_in[6];
    const float* wv    = (const float*)d_in[7];
    const float* bv    = (const float*)d_in[8];
    const float* wp    = (const float*)d_in[9];
    const float* bp    = (const float*)d_in[10];
    float* out = (float*)d_out;

    __nv_bfloat16 *xnt, *qt, *kt, *v, *at, *ot, *bwq, *bwk, *bwv, *bwp;
    float* e;
    cudaGetSymbolAddress((void**)&xnt, g_xnt);
    cudaGetSymbolAddress((void**)&qt,  g_qt);
    cudaGetSymbolAddress((void**)&kt,  g_kt);
    cudaGetSymbolAddress((void**)&v,   g_v);
    cudaGetSymbolAddress((void**)&e,   g_e);
    cudaGetSymbolAddress((void**)&at,  g_at);
    cudaGetSymbolAddress((void**)&ot,  g_ot);
    cudaGetSymbolAddress((void**)&bwq, g_wq);
    cudaGetSymbolAddress((void**)&bwk, g_wk);
    cudaGetSymbolAddress((void**)&bwv, g_wv);
    cudaGetSymbolAddress((void**)&bwp, g_wp);

    const long long sSC = (long long)HW_ * C_;    // 524288
    const long long sHH = (long long)HW_ * HW_;   // 1048576
    const float scale = 1.0f / sqrtf((float)C_);

    convert_w<<<256, 256>>>(wq, wk, wv, wp);
    gn_t_kernel<<<B_ * NG_, 256>>>(x, gamma, beta);

    // q_t[s,o], k_t[s,o]: M=1024 (s), N=512 (o), K=512, bias over n
    dim3 gqk(C_ / 128, HW_ / 128, B_);
    bf_gemm<2, false, true><<<gqk, 256>>>(
        xnt, bwq, qt, bq, nullptr, C_, C_, C_, C_, 1.0f, sSC, 0, sSC);
    bf_gemm<2, false, true><<<gqk, 256>>>(
        xnt, bwk, kt, bk, nullptr, C_, C_, C_, C_, 1.0f, sSC, 0, sSC);

    // v[o,s]: M=512 (o), N=1024 (s), K=512, bias over m
    dim3 gv(HW_ / 128, C_ / 128, B_);
    bf_gemm<1, false, true><<<gv, 256>>>(
        bwv, xnt, v, bv, nullptr, C_, C_, C_, HW_, 1.0f, 0, sSC, sSC);

    // e[i,j]: M=N=1024, K=512, fp32 out, alpha=scale
    dim3 ge(HW_ / 128, HW_ / 128, B_);
    bf_gemm<0, false, false><<<ge, 256>>>(
        qt, kt, e, nullptr, nullptr, C_, C_, C_, HW_, scale, sSC, sSC, sHH);

    softmax_kernel<<<B_ * HW_, 256>>>(e, at);

    // o_t[i,c]: M=1024 (i), N=512 (c), K=1024
    dim3 go(C_ / 128, HW_ / 128, B_);
    bf_gemm<0, false, true><<<go, 256>>>(
        at, v, ot, nullptr, nullptr, HW_, HW_, HW_, C_, 1.0f, sHH, sSC, sSC);

    // out[o,s]: M=512, N=1024, K=512, bias m, residual
    dim3 gp(HW_ / 128, C_ / 128, B_);
    bf_gemm<1, true, false><<<gp, 256>>>(
        bwp, ot, out, bp, x, C_, C_, C_, HW_, 1.0f, 0, sSC, sSC);
}

// round 5
// speedup vs baseline: 5.6855x; 1.1138x over previous
#include <cuda_runtime.h>
#include <cuda_bf16.h>
#include <cstdint>
#include <math.h>

// ---------------------------------------------------------------------------
// Attention block, bf16 mma.sync pipeline, 5-stage cp.async ring.
// B=16, C=512, HW=1024, 32 groups, eps=1e-6
// Every GEMM is D = A * B^T with both operands k-contiguous bf16.
// ---------------------------------------------------------------------------

#define B_ 16
#define C_ 512
#define HW_ 1024
#define NG_ 32

__device__ __nv_bfloat16 g_xnt[(long long)B_ * HW_ * C_];
__device__ __nv_bfloat16 g_qt [(long long)B_ * HW_ * C_];
__device__ __nv_bfloat16 g_kt [(long long)B_ * HW_ * C_];
__device__ __nv_bfloat16 g_v  [(long long)B_ * C_ * HW_];
__device__ float         g_e  [(long long)B_ * HW_ * HW_];
__device__ __nv_bfloat16 g_at [(long long)B_ * HW_ * HW_];
__device__ __nv_bfloat16 g_ot [(long long)B_ * HW_ * C_];
__device__ __nv_bfloat16 g_wq[C_ * C_], g_wk[C_ * C_], g_wv[C_ * C_], g_wp[C_ * C_];

__inline__ __device__ float warp_sum(float v) {
    #pragma unroll
    for (int o = 16; o > 0; o >>= 1) v += __shfl_xor_sync(0xffffffffu, v, o);
    return v;
}
__inline__ __device__ float warp_max(float v) {
    #pragma unroll
    for (int o = 16; o > 0; o >>= 1) v = fmaxf(v, __shfl_xor_sync(0xffffffffu, v, o));
    return v;
}
__device__ __forceinline__ uint32_t smem_u32(const void* p) {
    uint32_t a;
    asm("{ .reg .u64 t; cvta.to.shared.u64 t, %1; cvt.u32.u64 %0, t; }"
        : "=r"(a) : "l"(p));
    return a;
}

#define CPA16(dst, src) \
    asm volatile("cp.async.cg.shared.global [%0], [%1], 16;" :: "r"(dst), "l"(src))
#define CPA_COMMIT() asm volatile("cp.async.commit_group;" ::: "memory")

#define LDSM4(R0, R1, R2, R3, addr) \
    asm volatile("ldmatrix.sync.aligned.m8n8.x4.shared.b16 {%0,%1,%2,%3}, [%4];" \
                 : "=r"(R0), "=r"(R1), "=r"(R2), "=r"(R3) : "r"(addr))

__device__ __forceinline__ void mma_bf16(float c[4], const uint32_t a[4],
                                         uint32_t b0, uint32_t b1) {
    asm volatile(
        "mma.sync.aligned.m16n8k16.row.col.f32.bf16.bf16.f32 "
        "{%0,%1,%2,%3}, {%4,%5,%6,%7}, {%8,%9}, {%0,%1,%2,%3};"
        : "+f"(c[0]), "+f"(c[1]), "+f"(c[2]), "+f"(c[3])
        : "r"(a[0]), "r"(a[1]), "r"(a[2]), "r"(a[3]), "r"(b0), "r"(b1));
}

// ---------------------------------------------------------------------------
// Weight conversion fp32 -> bf16
// ---------------------------------------------------------------------------
__global__ void convert_w(const float* __restrict__ wq, const float* __restrict__ wk,
                          const float* __restrict__ wv, const float* __restrict__ wp)
{
    int i = (blockIdx.x * 256 + threadIdx.x) * 4;
    if (i >= C_ * C_) return;
    #pragma unroll
    for (int j = 0; j < 4; j++) {
        g_wq[i + j] = __float2bfloat16_rn(wq[i + j]);
        g_wk[i + j] = __float2bfloat16_rn(wk[i + j]);
        g_wv[i + j] = __float2bfloat16_rn(wv[i + j]);
        g_wp[i + j] = __float2bfloat16_rn(wp[i + j]);
    }
}

// ---------------------------------------------------------------------------
// GroupNorm + transpose: x (B,C,HW) fp32 -> xn_t (B,HW,C) bf16
// ---------------------------------------------------------------------------
__global__ void gn_t_kernel(const float* __restrict__ x,
                            const float* __restrict__ gamma,
                            const float* __restrict__ beta)
{
    const int GSZ = 16 * HW_;
    int bg = blockIdx.x;
    int b = bg >> 5, g = bg & 31;
    long long base = (long long)bg * GSZ;
    int tid = threadIdx.x;

    float s = 0.f, sq = 0.f;
    for (int e = tid * 4; e < GSZ; e += 256 * 4) {
        float4 v4 = *reinterpret_cast<const float4*>(&x[base + e]);
        s  += v4.x + v4.y + v4.z + v4.w;
        sq += v4.x * v4.x + v4.y * v4.y + v4.z * v4.z + v4.w * v4.w;
    }
    __shared__ float shs[8], shq[8];
    s = warp_sum(s); sq = warp_sum(sq);
    int wid = tid >> 5, lid = tid & 31;
    if (lid == 0) { shs[wid] = s; shq[wid] = sq; }
    __syncthreads();
    if (wid == 0) {
        float a = (lid < 8) ? shs[lid] : 0.f;
        float bb = (lid < 8) ? shq[lid] : 0.f;
        a = warp_sum(a); bb = warp_sum(bb);
        if (lid == 0) { shs[0] = a; shq[0] = bb; }
    }
    __syncthreads();
    float mean = shs[0] / (float)GSZ;
    float var  = shq[0] / (float)GSZ - mean * mean;
    float inv  = rsqrtf(var + 1e-6f);

    float ga[16], be[16];
    #pragma unroll
    for (int c = 0; c < 16; c++) {
        ga[c] = gamma[g * 16 + c] * inv;
        be[c] = beta[g * 16 + c] - mean * ga[c];
    }

    __shared__ float tile[16][256];
    for (int s0 = 0; s0 < HW_; s0 += 256) {
        __syncthreads();
        #pragma unroll
        for (int i = 0; i < 16; i++) {
            int task = tid + i * 256;
            int c = task >> 8, sl = task & 255;
            tile[c][sl] = x[base + (long long)c * HW_ + s0 + sl];
        }
        __syncthreads();
        int sp = s0 + tid;
        union { __nv_bfloat16 h[16]; uint4 u[2]; } o;
        #pragma unroll
        for (int c = 0; c < 16; c++)
            o.h[c] = __float2bfloat16_rn(tile[c][tid] * ga[c] + be[c]);
        uint4* dst = reinterpret_cast<uint4*>(
            &g_xnt[((long long)b * HW_ + sp) * C_ + g * 16]);
        dst[0] = o.u[0];
        dst[1] = o.u[1];
    }
}

// ---------------------------------------------------------------------------
// bf16 GEMM, 5-stage cp.async pipeline.
//   D[m,n] = alpha * sum_k A[m,k]*B[n,k] (+bias) (+res)
// CTA 128x128, BK=32, 8 warps (4M x 2N), warp tile 32x64.
// BIAS_MODE: 0 none, 1 bias[m], 2 bias[n]. OUT_BF16: out dtype.
// DUAL: blockIdx.z>>4 selects {Bm,bias,Cv} vs {Bm2,bias2,Cv2}; batch=z&15.
// ---------------------------------------------------------------------------
#define BK 32
#define ROWE 40                   // padded row in bf16 elems (80B)
#define STGE (128 * ROWE)         // elems per operand per stage
#define NSTAGE 5
#define SMEM_BYTES (2 * NSTAGE * STGE * 2)

__device__ __forceinline__ void fill_stage(
    uint32_t abase, uint32_t bbase,
    const __nv_bfloat16* Ap, const __nv_bfloat16* Bp,
    int m0, int n0, int ldA, int ldB, int k0, int tid)
{
    #pragma unroll
    for (int i = 0; i < 2; i++) {
        int task = tid + i * 256;
        int row = task >> 2, kc = task & 3;
        CPA16(abase + (row * ROWE + kc * 8) * 2,
              Ap + (long long)(m0 + row) * ldA + k0 + kc * 8);
        CPA16(bbase + (row * ROWE + kc * 8) * 2,
              Bp + (long long)(n0 + row) * ldB + k0 + kc * 8);
    }
}

template<int BIAS_MODE, bool HAS_RES, bool OUT_BF16, bool DUAL>
__global__ __launch_bounds__(256, 2) void bf_gemm(
    const __nv_bfloat16* __restrict__ A, const __nv_bfloat16* __restrict__ Bm,
    void* __restrict__ Cv, const float* __restrict__ bias,
    const float* __restrict__ resid,
    const __nv_bfloat16* __restrict__ Bm2, const float* __restrict__ bias2,
    void* __restrict__ Cv2,
    int K, int ldA, int ldB, int N, float alpha,
    long long sA, long long sB, long long sC)
{
    extern __shared__ __nv_bfloat16 dsm[];

    int tid = threadIdx.x, wid = tid >> 5, lane = tid & 31;
    int g = lane >> 2, t = lane & 3;
    int wm = (wid & 3) * 32;
    int wn = (wid >> 2) * 64;
    int n0 = blockIdx.x * 128;
    int m0 = blockIdx.y * 128;
    int bz = blockIdx.z;
    if (DUAL) {
        if (bz >> 4) { Bm = Bm2; bias = bias2; Cv = Cv2; }
        bz &= 15;
    }
    const __nv_bfloat16* Ap = A  + (long long)bz * sA;
    const __nv_bfloat16* Bp = Bm + (long long)bz * sB;

    uint32_t as_base = smem_u32(dsm);
    uint32_t bs_base = as_base + NSTAGE * STGE * 2;

    float acc[2][8][4];
    #pragma unroll
    for (int a = 0; a < 2; a++)
        #pragma unroll
        for (int b = 0; b < 8; b++)
            #pragma unroll
            for (int c = 0; c < 4; c++) acc[a][b][c] = 0.f;

    int nt = K / BK;

    // prologue: stages 0..3
    #pragma unroll
    for (int s = 0; s < NSTAGE - 1; s++) {
        fill_stage(as_base + s * STGE * 2, bs_base + s * STGE * 2,
                   Ap, Bp, m0, n0, ldA, ldB, s * BK, tid);
        CPA_COMMIT();
    }

    for (int tt = 0; tt < nt; tt++) {
        asm volatile("cp.async.wait_group %0;" :: "n"(NSTAGE - 2) : "memory");
        __syncthreads();

        int fs = tt + NSTAGE - 1;
        if (fs < nt) {
            int st = fs % NSTAGE;
            fill_stage(as_base + st * STGE * 2, bs_base + st * STGE * 2,
                       Ap, Bp, m0, n0, ldA, ldB, fs * BK, tid);
        }
        CPA_COMMIT();   // possibly empty: keeps group counts uniform

        int cs = tt % NSTAGE;
        uint32_t ab = as_base + cs * STGE * 2;
        uint32_t bb = bs_base + cs * STGE * 2;
        #pragma unroll
        for (int ks = 0; ks < BK; ks += 16) {
            uint32_t afr[2][4];
            #pragma unroll
            for (int mi = 0; mi < 2; mi++) {
                uint32_t addr = ab +
                    (((wm + mi * 16 + (lane & 15)) * ROWE) + ks + (lane >> 4) * 8) * 2;
                LDSM4(afr[mi][0], afr[mi][1], afr[mi][2], afr[mi][3], addr);
            }
            #pragma unroll
            for (int np = 0; np < 4; np++) {
                uint32_t b0, b1, b2, b3;
                uint32_t addr = bb +
                    (((wn + np * 16 + ((lane >> 4) << 3) + (lane & 7)) * ROWE)
                     + ks + ((lane >> 3) & 1) * 8) * 2;
                LDSM4(b0, b1, b2, b3, addr);
                mma_bf16(acc[0][np * 2], afr[0], b0, b1);
                mma_bf16(acc[1][np * 2], afr[1], b0, b1);
                mma_bf16(acc[0][np * 2 + 1], afr[0], b2, b3);
                mma_bf16(acc[1][np * 2 + 1], afr[1], b2, b3);
            }
        }
        __syncthreads();
    }

    // epilogue
    const float* Rp = HAS_RES ? (resid + (long long)bz * sC) : nullptr;
    float* Cf = OUT_BF16 ? nullptr : ((float*)Cv + (long long)bz * sC);
    __nv_bfloat16* Ch = OUT_BF16 ? ((__nv_bfloat16*)Cv + (long long)bz * sC) : nullptr;

    #pragma unroll
    for (int mi = 0; mi < 2; mi++) {
        int mlo = m0 + wm + mi * 16 + g;
        int mhi = mlo + 8;
        float bmlo = (BIAS_MODE == 1) ? bias[mlo] : 0.f;
        float bmhi = (BIAS_MODE == 1) ? bias[mhi] : 0.f;
        #pragma unroll
        for (int ni = 0; ni < 8; ni++) {
            int col = n0 + wn + ni * 8 + 2 * t;
            float bn0 = (BIAS_MODE == 2) ? bias[col] : 0.f;
            float bn1 = (BIAS_MODE == 2) ? bias[col + 1] : 0.f;
            float v00 = acc[mi][ni][0] * alpha + bmlo + bn0;
            float v01 = acc[mi][ni][1] * alpha + bmlo + bn1;
            float v10 = acc[mi][ni][2] * alpha + bmhi + bn0;
            float v11 = acc[mi][ni][3] * alpha + bmhi + bn1;
            long long olo = (long long)mlo * N + col;
            long long ohi = (long long)mhi * N + col;
            if (HAS_RES) {
                float2 r0 = *reinterpret_cast<const float2*>(&Rp[olo]);
                float2 r1 = *reinterpret_cast<const float2*>(&Rp[ohi]);
                v00 += r0.x; v01 += r0.y; v10 += r1.x; v11 += r1.y;
            }
            if (OUT_BF16) {
                __nv_bfloat162 plo(__float2bfloat16_rn(v00), __float2bfloat16_rn(v01));
                __nv_bfloat162 phi(__float2bfloat16_rn(v10), __float2bfloat16_rn(v11));
                *reinterpret_cast<__nv_bfloat162*>(&Ch[olo]) = plo;
                *reinterpret_cast<__nv_bfloat162*>(&Ch[ohi]) = phi;
            } else {
                *reinterpret_cast<float2*>(&Cf[olo]) = make_float2(v00, v01);
                *reinterpret_cast<float2*>(&Cf[ohi]) = make_float2(v10, v11);
            }
        }
    }
}

// ---------------------------------------------------------------------------
// Row softmax: e fp32 -> attn bf16
// ---------------------------------------------------------------------------
__global__ void softmax_kernel(const float* __restrict__ e,
                               __nv_bfloat16* __restrict__ at)
{
    long long row = (long long)blockIdx.x * HW_;
    const float* p = e + row;
    int t = threadIdx.x;

    float4 v4 = *reinterpret_cast<const float4*>(&p[t * 4]);
    float m = fmaxf(fmaxf(v4.x, v4.y), fmaxf(v4.z, v4.w));
    __shared__ float sh[8];
    m = warp_max(m);
    int wid = t >> 5, lid = t & 31;
    if (lid == 0) sh[wid] = m;
    __syncthreads();
    if (wid == 0) {
        float a = (lid < 8) ? sh[lid] : -3.4e38f;
        a = warp_max(a);
        if (lid == 0) sh[0] = a;
    }
    __syncthreads();
    m = sh[0];
    __syncthreads();

    v4.x = __expf(v4.x - m);
    v4.y = __expf(v4.y - m);
    v4.z = __expf(v4.z - m);
    v4.w = __expf(v4.w - m);
    float s = v4.x + v4.y + v4.z + v4.w;
    s = warp_sum(s);
    if (lid == 0) sh[wid] = s;
    __syncthreads();
    if (wid == 0) {
        float a = (lid < 8) ? sh[lid] : 0.f;
        a = warp_sum(a);
        if (lid == 0) sh[0] = a;
    }
    __syncthreads();
    float inv = 1.0f / sh[0];

    __nv_bfloat162 p0(__float2bfloat16_rn(v4.x * inv), __float2bfloat16_rn(v4.y * inv));
    __nv_bfloat162 p1(__float2bfloat16_rn(v4.z * inv), __float2bfloat16_rn(v4.w * inv));
    __nv_bfloat162* dst = reinterpret_cast<__nv_bfloat162*>(&at[row + t * 4]);
    dst[0] = p0;
    dst[1] = p1;
}

// ---------------------------------------------------------------------------
// Launch
// ---------------------------------------------------------------------------
extern "C" void kernel_launch(void* const* d_in, const int* in_sizes, int n_in,
                              void* d_out, int out_size)
{
    const float* x     = (const float*)d_in[0];
    const float* gamma = (const float*)d_in[1];
    const float* beta  = (const float*)d_in[2];
    const float* wq    = (const float*)d_in[3];
    const float* bq    = (const float*)d_in[4];
    const float* wk    = (const float*)d_in[5];
    const float* bk    = (const float*)d_in[6];
    const float* wv    = (const float*)d_in[7];
    const float* bv    = (const float*)d_in[8];
    const float* wp    = (const float*)d_in[9];
    const float* bp    = (const float*)d_in[10];
    float* out = (float*)d_out;

    __nv_bfloat16 *xnt, *qt, *kt, *v, *at, *ot, *bwq, *bwk, *bwv, *bwp;
    float* e;
    cudaGetSymbolAddress((void**)&xnt, g_xnt);
    cudaGetSymbolAddress((void**)&qt,  g_qt);
    cudaGetSymbolAddress((void**)&kt,  g_kt);
    cudaGetSymbolAddress((void**)&v,   g_v);
    cudaGetSymbolAddress((void**)&e,   g_e);
    cudaGetSymbolAddress((void**)&at,  g_at);
    cudaGetSymbolAddress((void**)&ot,  g_ot);
    cudaGetSymbolAddress((void**)&bwq, g_wq);
    cudaGetSymbolAddress((void**)&bwk, g_wk);
    cudaGetSymbolAddress((void**)&bwv, g_wv);
    cudaGetSymbolAddress((void**)&bwp, g_wp);

    const long long sSC = (long long)HW_ * C_;
    const long long sHH = (long long)HW_ * HW_;
    const float scale = 1.0f / sqrtf((float)C_);

    // raise dynamic smem limits (idempotent host-side calls; not allocations)
    cudaFuncSetAttribute(bf_gemm<2, false, true, true>,
                         cudaFuncAttributeMaxDynamicSharedMemorySize, SMEM_BYTES);
    cudaFuncSetAttribute(bf_gemm<1, false, true, false>,
                         cudaFuncAttributeMaxDynamicSharedMemorySize, SMEM_BYTES);
    cudaFuncSetAttribute(bf_gemm<0, false, false, false>,
                         cudaFuncAttributeMaxDynamicSharedMemorySize, SMEM_BYTES);
    cudaFuncSetAttribute(bf_gemm<0, false, true, false>,
                         cudaFuncAttributeMaxDynamicSharedMemorySize, SMEM_BYTES);
    cudaFuncSetAttribute(bf_gemm<1, true, false, false>,
                         cudaFuncAttributeMaxDynamicSharedMemorySize, SMEM_BYTES);

    convert_w<<<256, 256>>>(wq, wk, wv, wp);
    gn_t_kernel<<<B_ * NG_, 256>>>(x, gamma, beta);

    // q_t and k_t fused: M=1024(s), N=512(o), K=512; z<16 -> q, z>=16 -> k
    dim3 gqk(C_ / 128, HW_ / 128, 2 * B_);
    bf_gemm<2, false, true, true><<<gqk, 256, SMEM_BYTES>>>(
        xnt, bwq, qt, bq, nullptr, bwk, bk, kt,
        C_, C_, C_, C_, 1.0f, sSC, 0, sSC);

    // v[o,s]: M=512, N=1024, K=512, bias over m
    dim3 gv(HW_ / 128, C_ / 128, B_);
    bf_gemm<1, false, true, false><<<gv, 256, SMEM_BYTES>>>(
        bwv, xnt, v, bv, nullptr, nullptr, nullptr, nullptr,
        C_, C_, C_, HW_, 1.0f, 0, sSC, sSC);

    // e[i,j]: M=N=1024, K=512, fp32 out, alpha=scale
    dim3 ge(HW_ / 128, HW_ / 128, B_);
    bf_gemm<0, false, false, false><<<ge, 256, SMEM_BYTES>>>(
        qt, kt, e, nullptr, nullptr, nullptr, nullptr, nullptr,
        C_, C_, C_, HW_, scale, sSC, sSC, sHH);

    softmax_kernel<<<B_ * HW_, 256>>>(e, at);

    // o_t[i,c]: M=1024, N=512, K=1024
    dim3 go(C_ / 128, HW_ / 128, B_);
    bf_gemm<0, false, true, false><<<go, 256, SMEM_BYTES>>>(
        at, v, ot, nullptr, nullptr, nullptr, nullptr, nullptr,
        HW_, HW_, HW_, C_, 1.0f, sHH, sSC, sSC);

    // out[o,s]: M=512, N=1024, K=512, bias m, residual
    dim3 gp(HW_ / 128, C_ / 128, B_);
    bf_gemm<1, true, false, false><<<gp, 256, SMEM_BYTES>>>(
        bwp, ot, out, bp, x, nullptr, nullptr, nullptr,
        C_, C_, C_, HW_, 1.0f, 0, sSC, sSC);
}

// round 6
// speedup vs baseline: 6.0819x; 1.0697x over previous
#include <cuda_runtime.h>
#include <cuda_bf16.h>
#include <cstdint>
#include <math.h>

// ---------------------------------------------------------------------------
// Attention block, bf16 mma.sync pipeline, 5-stage cp.async ring,
// single-sync mainloop + software-pipelined ldmatrix.
// B=16, C=512, HW=1024, 32 groups, eps=1e-6
// ---------------------------------------------------------------------------

#define B_ 16
#define C_ 512
#define HW_ 1024
#define NG_ 32

__device__ __nv_bfloat16 g_xnt[(long long)B_ * HW_ * C_];
__device__ __nv_bfloat16 g_qt [(long long)B_ * HW_ * C_];
__device__ __nv_bfloat16 g_kt [(long long)B_ * HW_ * C_];
__device__ __nv_bfloat16 g_v  [(long long)B_ * C_ * HW_];
__device__ float         g_e  [(long long)B_ * HW_ * HW_];
__device__ __nv_bfloat16 g_at [(long long)B_ * HW_ * HW_];
__device__ __nv_bfloat16 g_ot [(long long)B_ * HW_ * C_];
__device__ __nv_bfloat16 g_wq[C_ * C_], g_wk[C_ * C_], g_wv[C_ * C_], g_wp[C_ * C_];

__inline__ __device__ float warp_sum(float v) {
    #pragma unroll
    for (int o = 16; o > 0; o >>= 1) v += __shfl_xor_sync(0xffffffffu, v, o);
    return v;
}
__inline__ __device__ float warp_max(float v) {
    #pragma unroll
    for (int o = 16; o > 0; o >>= 1) v = fmaxf(v, __shfl_xor_sync(0xffffffffu, v, o));
    return v;
}
__device__ __forceinline__ uint32_t smem_u32(const void* p) {
    uint32_t a;
    asm("{ .reg .u64 t; cvta.to.shared.u64 t, %1; cvt.u32.u64 %0, t; }"
        : "=r"(a) : "l"(p));
    return a;
}

#define CPA16(dst, src) \
    asm volatile("cp.async.cg.shared.global [%0], [%1], 16;" :: "r"(dst), "l"(src))
#define CPA_COMMIT() asm volatile("cp.async.commit_group;" ::: "memory")

#define LDSM4(R0, R1, R2, R3, addr) \
    asm volatile("ldmatrix.sync.aligned.m8n8.x4.shared.b16 {%0,%1,%2,%3}, [%4];" \
                 : "=r"(R0), "=r"(R1), "=r"(R2), "=r"(R3) : "r"(addr))

__device__ __forceinline__ void mma_bf16(float c[4], const uint32_t a[4],
                                         uint32_t b0, uint32_t b1) {
    asm volatile(
        "mma.sync.aligned.m16n8k16.row.col.f32.bf16.bf16.f32 "
        "{%0,%1,%2,%3}, {%4,%5,%6,%7}, {%8,%9}, {%0,%1,%2,%3};"
        : "+f"(c[0]), "+f"(c[1]), "+f"(c[2]), "+f"(c[3])
        : "r"(a[0]), "r"(a[1]), "r"(a[2]), "r"(a[3]), "r"(b0), "r"(b1));
}

// ---------------------------------------------------------------------------
// Weight conversion fp32 -> bf16
// ---------------------------------------------------------------------------
__global__ void convert_w(const float* __restrict__ wq, const float* __restrict__ wk,
                          const float* __restrict__ wv, const float* __restrict__ wp)
{
    int i = (blockIdx.x * 256 + threadIdx.x) * 4;
    if (i >= C_ * C_) return;
    #pragma unroll
    for (int j = 0; j < 4; j++) {
        g_wq[i + j] = __float2bfloat16_rn(wq[i + j]);
        g_wk[i + j] = __float2bfloat16_rn(wk[i + j]);
        g_wv[i + j] = __float2bfloat16_rn(wv[i + j]);
        g_wp[i + j] = __float2bfloat16_rn(wp[i + j]);
    }
}

// ---------------------------------------------------------------------------
// GroupNorm + transpose: x (B,C,HW) fp32 -> xn_t (B,HW,C) bf16
// ---------------------------------------------------------------------------
__global__ void gn_t_kernel(const float* __restrict__ x,
                            const float* __restrict__ gamma,
                            const float* __restrict__ beta)
{
    const int GSZ = 16 * HW_;
    int bg = blockIdx.x;
    int b = bg >> 5, g = bg & 31;
    long long base = (long long)bg * GSZ;
    int tid = threadIdx.x;

    float s = 0.f, sq = 0.f;
    for (int e = tid * 4; e < GSZ; e += 256 * 4) {
        float4 v4 = *reinterpret_cast<const float4*>(&x[base + e]);
        s  += v4.x + v4.y + v4.z + v4.w;
        sq += v4.x * v4.x + v4.y * v4.y + v4.z * v4.z + v4.w * v4.w;
    }
    __shared__ float shs[8], shq[8];
    s = warp_sum(s); sq = warp_sum(sq);
    int wid = tid >> 5, lid = tid & 31;
    if (lid == 0) { shs[wid] = s; shq[wid] = sq; }
    __syncthreads();
    if (wid == 0) {
        float a = (lid < 8) ? shs[lid] : 0.f;
        float bb = (lid < 8) ? shq[lid] : 0.f;
        a = warp_sum(a); bb = warp_sum(bb);
        if (lid == 0) { shs[0] = a; shq[0] = bb; }
    }
    __syncthreads();
    float mean = shs[0] / (float)GSZ;
    float var  = shq[0] / (float)GSZ - mean * mean;
    float inv  = rsqrtf(var + 1e-6f);

    float ga[16], be[16];
    #pragma unroll
    for (int c = 0; c < 16; c++) {
        ga[c] = gamma[g * 16 + c] * inv;
        be[c] = beta[g * 16 + c] - mean * ga[c];
    }

    __shared__ float tile[16][256];
    for (int s0 = 0; s0 < HW_; s0 += 256) {
        __syncthreads();
        #pragma unroll
        for (int i = 0; i < 16; i++) {
            int task = tid + i * 256;
            int c = task >> 8, sl = task & 255;
            tile[c][sl] = x[base + (long long)c * HW_ + s0 + sl];
        }
        __syncthreads();
        int sp = s0 + tid;
        union { __nv_bfloat16 h[16]; uint4 u[2]; } o;
        #pragma unroll
        for (int c = 0; c < 16; c++)
            o.h[c] = __float2bfloat16_rn(tile[c][tid] * ga[c] + be[c]);
        uint4* dst = reinterpret_cast<uint4*>(
            &g_xnt[((long long)b * HW_ + sp) * C_ + g * 16]);
        dst[0] = o.u[0];
        dst[1] = o.u[1];
    }
}

// ---------------------------------------------------------------------------
// bf16 GEMM, 5-stage cp.async pipeline, 1 sync/iter, pipelined ldmatrix.
// ---------------------------------------------------------------------------
#define BK 32
#define ROWE 40                   // padded row in bf16 elems (80B)
#define STGE (128 * ROWE)
#define NSTAGE 5
#define SMEM_BYTES (2 * NSTAGE * STGE * 2)

__device__ __forceinline__ void fill_stage(
    uint32_t abase, uint32_t bbase,
    const __nv_bfloat16* Ap, const __nv_bfloat16* Bp,
    int m0, int n0, int ldA, int ldB, int k0, int tid)
{
    #pragma unroll
    for (int i = 0; i < 2; i++) {
        int task = tid + i * 256;
        int row = task >> 2, kc = task & 3;
        CPA16(abase + (row * ROWE + kc * 8) * 2,
              Ap + (long long)(m0 + row) * ldA + k0 + kc * 8);
        CPA16(bbase + (row * ROWE + kc * 8) * 2,
              Bp + (long long)(n0 + row) * ldB + k0 + kc * 8);
    }
}

template<int BIAS_MODE, bool HAS_RES, bool OUT_BF16, bool DUAL>
__global__ __launch_bounds__(256, 2) void bf_gemm(
    const __nv_bfloat16* __restrict__ A, const __nv_bfloat16* __restrict__ Bm,
    void* __restrict__ Cv, const float* __restrict__ bias,
    const float* __restrict__ resid,
    const __nv_bfloat16* __restrict__ Bm2, const float* __restrict__ bias2,
    void* __restrict__ Cv2,
    int K, int ldA, int ldB, int N, float alpha,
    long long sA, long long sB, long long sC)
{
    extern __shared__ __nv_bfloat16 dsm[];

    int tid = threadIdx.x, wid = tid >> 5, lane = tid & 31;
    int g = lane >> 2, t = lane & 3;
    int wm = (wid & 3) * 32;
    int wn = (wid >> 2) * 64;
    int n0 = blockIdx.x * 128;
    int m0 = blockIdx.y * 128;
    int bz = blockIdx.z;
    if (DUAL) {
        if (bz >> 4) { Bm = Bm2; bias = bias2; Cv = Cv2; }
        bz &= 15;
    }
    const __nv_bfloat16* Ap = A  + (long long)bz * sA;
    const __nv_bfloat16* Bp = Bm + (long long)bz * sB;

    uint32_t as_base = smem_u32(dsm);
    uint32_t bs_base = as_base + NSTAGE * STGE * 2;

    // per-thread ldmatrix base offsets (element units)
    int a_row = wm + (lane & 15);
    int a_koff = (lane >> 4) * 8;
    int b_row = wn + ((lane >> 4) << 3) + (lane & 7);
    int b_koff = ((lane >> 3) & 1) * 8;

    float acc[2][8][4];
    #pragma unroll
    for (int a = 0; a < 2; a++)
        #pragma unroll
        for (int b = 0; b < 8; b++)
            #pragma unroll
            for (int c = 0; c < 4; c++) acc[a][b][c] = 0.f;

    int nt = K / BK;

    // prologue: fill stages 0..3
    #pragma unroll
    for (int s = 0; s < NSTAGE - 1; s++) {
        fill_stage(as_base + s * STGE * 2, bs_base + s * STGE * 2,
                   Ap, Bp, m0, n0, ldA, ldB, s * BK, tid);
        CPA_COMMIT();
    }
    asm volatile("cp.async.wait_group %0;" :: "n"(NSTAGE - 2) : "memory");
    __syncthreads();

    for (int tt = 0; tt < nt; tt++) {
        // fill the stage freed at the end of the previous iteration
        int fs = tt + NSTAGE - 1;
        if (fs < nt) {
            int st = fs % NSTAGE;
            fill_stage(as_base + st * STGE * 2, bs_base + st * STGE * 2,
                       Ap, Bp, m0, n0, ldA, ldB, fs * BK, tid);
        }
        CPA_COMMIT();

        int cs = tt % NSTAGE;
        uint32_t ab = as_base + cs * STGE * 2;
        uint32_t bb = bs_base + cs * STGE * 2;

        #pragma unroll
        for (int ks = 0; ks < BK; ks += 16) {
            // A fragments for this k-step
            uint32_t afr[2][4];
            #pragma unroll
            for (int mi = 0; mi < 2; mi++) {
                uint32_t addr = ab + (((a_row + mi * 16) * ROWE) + ks + a_koff) * 2;
                LDSM4(afr[mi][0], afr[mi][1], afr[mi][2], afr[mi][3], addr);
            }
            // software-pipelined B fragments over np
            uint32_t bcur[4], bnxt[4];
            {
                uint32_t addr = bb + ((b_row * ROWE) + ks + b_koff) * 2;
                LDSM4(bcur[0], bcur[1], bcur[2], bcur[3], addr);
            }
            #pragma unroll
            for (int np = 0; np < 4; np++) {
                if (np < 3) {
                    uint32_t addr = bb +
                        (((b_row + (np + 1) * 16) * ROWE) + ks + b_koff) * 2;
                    LDSM4(bnxt[0], bnxt[1], bnxt[2], bnxt[3], addr);
                }
                mma_bf16(acc[0][np * 2],     afr[0], bcur[0], bcur[1]);
                mma_bf16(acc[1][np * 2],     afr[1], bcur[0], bcur[1]);
                mma_bf16(acc[0][np * 2 + 1], afr[0], bcur[2], bcur[3]);
                mma_bf16(acc[1][np * 2 + 1], afr[1], bcur[2], bcur[3]);
                #pragma unroll
                for (int j = 0; j < 4; j++) bcur[j] = bnxt[j];
            }
        }

        asm volatile("cp.async.wait_group %0;" :: "n"(NSTAGE - 2) : "memory");
        __syncthreads();
    }

    // epilogue
    const float* Rp = HAS_RES ? (resid + (long long)bz * sC) : nullptr;
    float* Cf = OUT_BF16 ? nullptr : ((float*)Cv + (long long)bz * sC);
    __nv_bfloat16* Ch = OUT_BF16 ? ((__nv_bfloat16*)Cv + (long long)bz * sC) : nullptr;

    #pragma unroll
    for (int mi = 0; mi < 2; mi++) {
        int mlo = m0 + wm + mi * 16 + g;
        int mhi = mlo + 8;
        float bmlo = (BIAS_MODE == 1) ? bias[mlo] : 0.f;
        float bmhi = (BIAS_MODE == 1) ? bias[mhi] : 0.f;
        #pragma unroll
        for (int ni = 0; ni < 8; ni++) {
            int col = n0 + wn + ni * 8 + 2 * t;
            float bn0 = (BIAS_MODE == 2) ? bias[col] : 0.f;
            float bn1 = (BIAS_MODE == 2) ? bias[col + 1] : 0.f;
            float v00 = acc[mi][ni][0] * alpha + bmlo + bn0;
            float v01 = acc[mi][ni][1] * alpha + bmlo + bn1;
            float v10 = acc[mi][ni][2] * alpha + bmhi + bn0;
            float v11 = acc[mi][ni][3] * alpha + bmhi + bn1;
            long long olo = (long long)mlo * N + col;
            long long ohi = (long long)mhi * N + col;
            if (HAS_RES) {
                float2 r0 = *reinterpret_cast<const float2*>(&Rp[olo]);
                float2 r1 = *reinterpret_cast<const float2*>(&Rp[ohi]);
                v00 += r0.x; v01 += r0.y; v10 += r1.x; v11 += r1.y;
            }
            if (OUT_BF16) {
                __nv_bfloat162 plo(__float2bfloat16_rn(v00), __float2bfloat16_rn(v01));
                __nv_bfloat162 phi(__float2bfloat16_rn(v10), __float2bfloat16_rn(v11));
                *reinterpret_cast<__nv_bfloat162*>(&Ch[olo]) = plo;
                *reinterpret_cast<__nv_bfloat162*>(&Ch[ohi]) = phi;
            } else {
                *reinterpret_cast<float2*>(&Cf[olo]) = make_float2(v00, v01);
                *reinterpret_cast<float2*>(&Cf[ohi]) = make_float2(v10, v11);
            }
        }
    }
}

// ---------------------------------------------------------------------------
// Row softmax: e fp32 -> attn bf16
// ---------------------------------------------------------------------------
__global__ void softmax_kernel(const float* __restrict__ e,
                               __nv_bfloat16* __restrict__ at)
{
    long long row = (long long)blockIdx.x * HW_;
    const float* p = e + row;
    int t = threadIdx.x;

    float4 v4 = *reinterpret_cast<const float4*>(&p[t * 4]);
    float m = fmaxf(fmaxf(v4.x, v4.y), fmaxf(v4.z, v4.w));
    __shared__ float sh[8];
    m = warp_max(m);
    int wid = t >> 5, lid = t & 31;
    if (lid == 0) sh[wid] = m;
    __syncthreads();
    if (wid == 0) {
        float a = (lid < 8) ? sh[lid] : -3.4e38f;
        a = warp_max(a);
        if (lid == 0) sh[0] = a;
    }
    __syncthreads();
    m = sh[0];
    __syncthreads();

    v4.x = __expf(v4.x - m);
    v4.y = __expf(v4.y - m);
    v4.z = __expf(v4.z - m);
    v4.w = __expf(v4.w - m);
    float s = v4.x + v4.y + v4.z + v4.w;
    s = warp_sum(s);
    if (lid == 0) sh[wid] = s;
    __syncthreads();
    if (wid == 0) {
        float a = (lid < 8) ? sh[lid] : 0.f;
        a = warp_sum(a);
        if (lid == 0) sh[0] = a;
    }
    __syncthreads();
    float inv = 1.0f / sh[0];

    __nv_bfloat162 p0(__float2bfloat16_rn(v4.x * inv), __float2bfloat16_rn(v4.y * inv));
    __nv_bfloat162 p1(__float2bfloat16_rn(v4.z * inv), __float2bfloat16_rn(v4.w * inv));
    __nv_bfloat162* dst = reinterpret_cast<__nv_bfloat162*>(&at[row + t * 4]);
    dst[0] = p0;
    dst[1] = p1;
}

// ---------------------------------------------------------------------------
// Launch
// ---------------------------------------------------------------------------
extern "C" void kernel_launch(void* const* d_in, const int* in_sizes, int n_in,
                              void* d_out, int out_size)
{
    const float* x     = (const float*)d_in[0];
    const float* gamma = (const float*)d_in[1];
    const float* beta  = (const float*)d_in[2];
    const float* wq    = (const float*)d_in[3];
    const float* bq    = (const float*)d_in[4];
    const float* wk    = (const float*)d_in[5];
    const float* bk    = (const float*)d_in[6];
    const float* wv    = (const float*)d_in[7];
    const float* bv    = (const float*)d_in[8];
    const float* wp    = (const float*)d_in[9];
    const float* bp    = (const float*)d_in[10];
    float* out = (float*)d_out;

    __nv_bfloat16 *xnt, *qt, *kt, *v, *at, *ot, *bwq, *bwk, *bwv, *bwp;
    float* e;
    cudaGetSymbolAddress((void**)&xnt, g_xnt);
    cudaGetSymbolAddress((void**)&qt,  g_qt);
    cudaGetSymbolAddress((void**)&kt,  g_kt);
    cudaGetSymbolAddress((void**)&v,   g_v);
    cudaGetSymbolAddress((void**)&e,   g_e);
    cudaGetSymbolAddress((void**)&at,  g_at);
    cudaGetSymbolAddress((void**)&ot,  g_ot);
    cudaGetSymbolAddress((void**)&bwq, g_wq);
    cudaGetSymbolAddress((void**)&bwk, g_wk);
    cudaGetSymbolAddress((void**)&bwv, g_wv);
    cudaGetSymbolAddress((void**)&bwp, g_wp);

    const long long sSC = (long long)HW_ * C_;
    const long long sHH = (long long)HW_ * HW_;
    const float scale = 1.0f / sqrtf((float)C_);

    cudaFuncSetAttribute(bf_gemm<2, false, true, true>,
                         cudaFuncAttributeMaxDynamicSharedMemorySize, SMEM_BYTES);
    cudaFuncSetAttribute(bf_gemm<1, false, true, false>,
                         cudaFuncAttributeMaxDynamicSharedMemorySize, SMEM_BYTES);
    cudaFuncSetAttribute(bf_gemm<0, false, false, false>,
                         cudaFuncAttributeMaxDynamicSharedMemorySize, SMEM_BYTES);
    cudaFuncSetAttribute(bf_gemm<0, false, true, false>,
                         cudaFuncAttributeMaxDynamicSharedMemorySize, SMEM_BYTES);
    cudaFuncSetAttribute(bf_gemm<1, true, false, false>,
                         cudaFuncAttributeMaxDynamicSharedMemorySize, SMEM_BYTES);

    convert_w<<<256, 256>>>(wq, wk, wv, wp);
    gn_t_kernel<<<B_ * NG_, 256>>>(x, gamma, beta);

    // q_t and k_t fused: z<16 -> q, z>=16 -> k
    dim3 gqk(C_ / 128, HW_ / 128, 2 * B_);
    bf_gemm<2, false, true, true><<<gqk, 256, SMEM_BYTES>>>(
        xnt, bwq, qt, bq, nullptr, bwk, bk, kt,
        C_, C_, C_, C_, 1.0f, sSC, 0, sSC);

    // v[o,s]
    dim3 gv(HW_ / 128, C_ / 128, B_);
    bf_gemm<1, false, true, false><<<gv, 256, SMEM_BYTES>>>(
        bwv, xnt, v, bv, nullptr, nullptr, nullptr, nullptr,
        C_, C_, C_, HW_, 1.0f, 0, sSC, sSC);

    // e[i,j]
    dim3 ge(HW_ / 128, HW_ / 128, B_);
    bf_gemm<0, false, false, false><<<ge, 256, SMEM_BYTES>>>(
        qt, kt, e, nullptr, nullptr, nullptr, nullptr, nullptr,
        C_, C_, C_, HW_, scale, sSC, sSC, sHH);

    softmax_kernel<<<B_ * HW_, 256>>>(e, at);

    // o_t[i,c]
    dim3 go(C_ / 128, HW_ / 128, B_);
    bf_gemm<0, false, true, false><<<go, 256, SMEM_BYTES>>>(
        at, v, ot, nullptr, nullptr, nullptr, nullptr, nullptr,
        HW_, HW_, HW_, C_, 1.0f, sHH, sSC, sSC);

    // out[o,s] + residual
    dim3 gp(HW_ / 128, C_ / 128, B_);
    bf_gemm<1, true, false, false><<<gp, 256, SMEM_BYTES>>>(
        bwp, ot, out, bp, x, nullptr, nullptr, nullptr,
        C_, C_, C_, HW_, 1.0f, 0, sSC, sSC);
}